// round 2
// baseline (speedup 1.0000x reference)
#include <cuda_runtime.h>
#include <math.h>

#define TT 512
#define BB 32
#define II 512
#define HH 1024
#define BH (BB*HH)
#define TBH (TT*BB*HH)   // 16,777,216
#define NBLK 128
#define WROW 1032        // padded weight row (floats): 1032*4B -> 8-bank skew per row

typedef unsigned long long ull;

// ------------------------- device scratch (no allocations allowed) ----------
__device__ float g_P[(size_t)4 * TBH];   // 4 x [T][B][H] gate preactivations
__device__ float g_h[BH];                // hidden state
__device__ float g_c[2][BH];             // cell state ping-pong
__device__ float g_bias[4][HH];          // combined gate biases
__device__ unsigned g_bar_cnt;           // grid barrier arrival counter
__device__ unsigned g_bar_gen;           // grid barrier generation

// ------------------------- helpers -----------------------------------------
__device__ __forceinline__ ull ffma2(ull a, ull b, ull c) {
    ull d;
    asm("fma.rn.f32x2 %0, %1, %2, %3;" : "=l"(d) : "l"(a), "l"(b), "l"(c));
    return d;
}
__device__ __forceinline__ float fsum2(ull v) {
    float2 f = *(float2*)&v;
    return f.x + f.y;
}

__device__ __forceinline__ void grid_barrier(int tid) {
    __threadfence();                // make this thread's global writes visible
    __syncthreads();
    if (tid == 0) {
        unsigned g = *(volatile unsigned*)&g_bar_gen;
        unsigned old = atomicAdd(&g_bar_cnt, 1);
        if (old == NBLK - 1) {
            atomicExch(&g_bar_cnt, 0);
            __threadfence();
            atomicExch(&g_bar_gen, g + 1);
        } else {
            while (*(volatile unsigned*)&g_bar_gen == g) { __nanosleep(64); }
        }
    }
    __syncthreads();
}

// ------------------------- init --------------------------------------------
__global__ void __launch_bounds__(256) init_kernel(
    const float* __restrict__ h0, const float* __restrict__ c0,
    const float* __restrict__ b_ii, const float* __restrict__ b_hi,
    const float* __restrict__ b_ci, const float* __restrict__ b_if,
    const float* __restrict__ b_hf, const float* __restrict__ b_cf,
    const float* __restrict__ b_ic, const float* __restrict__ b_hc,
    const float* __restrict__ b_io, const float* __restrict__ b_ho,
    const float* __restrict__ b_cyo)
{
    int i = blockIdx.x * blockDim.x + threadIdx.x;
    if (i < BH) {
        g_h[i] = h0[i];
        g_c[0][i] = c0[i];
    }
    if (i < HH) {
        g_bias[0][i] = b_ii[i] + b_hi[i] + b_ci[i];
        g_bias[1][i] = b_if[i] + b_hf[i] + b_cf[i];
        g_bias[2][i] = b_ic[i] + b_hc[i];
        g_bias[3][i] = b_io[i] + b_ho[i] + b_cyo[i];
    }
    if (i == 0) { g_bar_cnt = 0; }
}

// ------------------------- proj: P = X @ W^T + bias ------------------------
// M=16384 (t*32+b), N'=4096 (4 gates x 1024), K=512. 128x128x8 SGEMM.
__global__ void __launch_bounds__(256) proj_kernel(
    const float* __restrict__ X,
    const float* __restrict__ Wii, const float* __restrict__ Wif,
    const float* __restrict__ Wic, const float* __restrict__ Wio)
{
    __shared__ float sA[8][128];
    __shared__ float sB[8][128];
    __shared__ float sBias[128];

    int tid = threadIdx.x;
    int bx = blockIdx.x;       // n tile (0..31)
    int by = blockIdx.y;       // m tile (0..127)
    int m0 = by * 128, n0 = bx * 128;

    if (tid < 128) {
        int np = n0 + tid;
        sBias[tid] = g_bias[np >> 10][np & 1023];
    }

    int lrow = tid >> 1;
    int lkq  = tid & 1;

    int np = n0 + lrow;
    int gsel = np >> 10;
    const float* wrow = (gsel == 0) ? Wii : (gsel == 1) ? Wif : (gsel == 2) ? Wic : Wio;
    wrow += (np & 1023) * II;

    const float* arow = X + (m0 + lrow) * II;

    int tx = tid & 15, ty = tid >> 4;

    float acc[8][8];
#pragma unroll
    for (int i = 0; i < 8; i++)
#pragma unroll
        for (int j = 0; j < 8; j++) acc[i][j] = 0.f;

    for (int k0 = 0; k0 < II; k0 += 8) {
        float4 av = *(const float4*)(arow + k0 + lkq * 4);
        float4 bv = *(const float4*)(wrow + k0 + lkq * 4);
        __syncthreads();
        sA[lkq * 4 + 0][lrow] = av.x; sA[lkq * 4 + 1][lrow] = av.y;
        sA[lkq * 4 + 2][lrow] = av.z; sA[lkq * 4 + 3][lrow] = av.w;
        sB[lkq * 4 + 0][lrow] = bv.x; sB[lkq * 4 + 1][lrow] = bv.y;
        sB[lkq * 4 + 2][lrow] = bv.z; sB[lkq * 4 + 3][lrow] = bv.w;
        __syncthreads();
#pragma unroll
        for (int kk = 0; kk < 8; kk++) {
            float a[8], b[8];
            *(float4*)(a)     = *(float4*)&sA[kk][ty * 4];
            *(float4*)(a + 4) = *(float4*)&sA[kk][64 + ty * 4];
            *(float4*)(b)     = *(float4*)&sB[kk][tx * 4];
            *(float4*)(b + 4) = *(float4*)&sB[kk][64 + tx * 4];
#pragma unroll
            for (int i = 0; i < 8; i++)
#pragma unroll
                for (int j = 0; j < 8; j++)
                    acc[i][j] = fmaf(a[i], b[j], acc[i][j]);
        }
    }

#pragma unroll
    for (int i = 0; i < 8; i++) {
        int m = m0 + ((i < 4) ? (ty * 4 + i) : (64 + ty * 4 + (i - 4)));
#pragma unroll
        for (int jh = 0; jh < 2; jh++) {
            int colbase = (jh ? 64 : 0) + tx * 4;
            int npc = n0 + colbase;
            int g = npc >> 10;
            int n = npc & 1023;
            float4 v;
            v.x = acc[i][jh * 4 + 0] + sBias[colbase + 0];
            v.y = acc[i][jh * 4 + 1] + sBias[colbase + 1];
            v.z = acc[i][jh * 4 + 2] + sBias[colbase + 2];
            v.w = acc[i][jh * 4 + 3] + sBias[colbase + 3];
            *(float4*)(g_P + (size_t)g * TBH + (size_t)m * HH + n) = v;
        }
    }
}

// ------------------------- persistent recurrence ---------------------------
// 128 blocks x 256 threads, 1 block/SM. Block owns 8 n-columns.
// Thread = (n_l = tid&7, b = tid>>3).
// SMEM: 6 weight mats [8][WROW] persistent + h/c chunk buffers [32][68].
#define SMEM_FLOATS (6*8*WROW + 2*32*68)

extern "C" __global__ void __launch_bounds__(256) lstm_kernel(
    const float* __restrict__ Whi, const float* __restrict__ Whf,
    const float* __restrict__ Whc, const float* __restrict__ Who,
    const float* __restrict__ Wci, const float* __restrict__ Wcf,
    const float* __restrict__ Wcyo, float* __restrict__ out)
{
    extern __shared__ float smem[];
    float* smw = smem;                   // 6*8*WROW
    float* sH  = smw + 6 * 8 * WROW;     // 32*68
    float* sC  = sH + 32 * 68;           // 32*68

    int tid = threadIdx.x;
    int n_l = tid & 7, b = tid >> 3;
    int n0 = blockIdx.x * 8;

    // ---- stage the 6 recurrent weight slices into SMEM once ----
    {
        const float* mats[6] = {Whi, Whf, Whc, Who, Wci, Wcf};
#pragma unroll
        for (int m = 0; m < 6; m++) {
            const float* src = mats[m] + (size_t)n0 * HH;
            float* dst = smw + m * 8 * WROW;
            for (int e = tid; e < 8 * 256; e += 256) {
                int r = e >> 8, kq = e & 255;
                *(float4*)(dst + r * WROW + kq * 4) =
                    *(const float4*)(src + r * HH + kq * 4);
            }
        }
    }
    __syncthreads();

    const float* p0 = smw + (0 * 8 + n_l) * WROW;   // w_hi
    const float* p1 = smw + (1 * 8 + n_l) * WROW;   // w_hf
    const float* p2 = smw + (2 * 8 + n_l) * WROW;   // w_hc
    const float* p3 = smw + (3 * 8 + n_l) * WROW;   // w_ho
    const float* p4 = smw + (4 * 8 + n_l) * WROW;   // w_ci
    const float* p5 = smw + (5 * 8 + n_l) * WROW;   // w_cf

    const int idx = b * HH + n0 + n_l;
    const float* wc = Wcyo + (size_t)(n0 + n_l) * HH;

    // staging assignments: thread stages rows sb0 and sb0+16, quad kq0
    const int sb0 = tid >> 4;        // 0..15
    const int kq0 = tid & 15;        // 0..15
    float* hdst0 = sH + sb0 * 68 + kq0 * 4;
    float* hdst1 = sH + (sb0 + 16) * 68 + kq0 * 4;
    float* cdst0 = sC + sb0 * 68 + kq0 * 4;
    float* cdst1 = sC + (sb0 + 16) * 68 + kq0 * 4;
    const float* shb = sH + b * 68;
    const float* scb = sC + b * 68;

    for (int t = 0; t < TT; t++) {
        const float* c_in  = g_c[t & 1];
        float*       c_out = g_c[(t + 1) & 1];
        size_t base = (size_t)t * BH + idx;

        float p_i = g_P[base];
        float p_f = g_P[(size_t)TBH + base];
        float p_g = g_P[2 * (size_t)TBH + base];
        float p_o = g_P[3 * (size_t)TBH + base];
        float cin_own = __ldcv(c_in + idx);

        ull a00 = 0, a01 = 0, a10 = 0, a11 = 0, a20 = 0, a21 = 0;
        ull a30 = 0, a31 = 0, a40 = 0, a41 = 0, a50 = 0, a51 = 0;

        // prefetch chunk 0 of h and c
        float4 rh0 = __ldcv((const float4*)(g_h  + sb0 * HH + kq0 * 4));
        float4 rh1 = __ldcv((const float4*)(g_h  + (sb0 + 16) * HH + kq0 * 4));
        float4 rc0 = __ldcv((const float4*)(c_in + sb0 * HH + kq0 * 4));
        float4 rc1 = __ldcv((const float4*)(c_in + (sb0 + 16) * HH + kq0 * 4));

        for (int j = 0; j < 16; j++) {
            int k0 = j * 64;
            __syncthreads();                // previous chunk's compute done
            *(float4*)hdst0 = rh0;
            *(float4*)hdst1 = rh1;
            *(float4*)cdst0 = rc0;
            *(float4*)cdst1 = rc1;
            __syncthreads();                // chunk visible
            if (j < 15) {
                int k1 = k0 + 64;
                rh0 = __ldcv((const float4*)(g_h  + sb0 * HH + k1 + kq0 * 4));
                rh1 = __ldcv((const float4*)(g_h  + (sb0 + 16) * HH + k1 + kq0 * 4));
                rc0 = __ldcv((const float4*)(c_in + sb0 * HH + k1 + kq0 * 4));
                rc1 = __ldcv((const float4*)(c_in + (sb0 + 16) * HH + k1 + kq0 * 4));
            }
#pragma unroll
            for (int kq = 0; kq < 16; kq++) {
                int ks = kq * 4;
                ulonglong2 h2 = *(const ulonglong2*)(shb + ks);
                ulonglong2 c2 = *(const ulonglong2*)(scb + ks);
                ulonglong2 w;
                w = *(const ulonglong2*)(p0 + k0 + ks);
                a00 = ffma2(h2.x, w.x, a00); a01 = ffma2(h2.y, w.y, a01);
                w = *(const ulonglong2*)(p1 + k0 + ks);
                a10 = ffma2(h2.x, w.x, a10); a11 = ffma2(h2.y, w.y, a11);
                w = *(const ulonglong2*)(p2 + k0 + ks);
                a20 = ffma2(h2.x, w.x, a20); a21 = ffma2(h2.y, w.y, a21);
                w = *(const ulonglong2*)(p3 + k0 + ks);
                a30 = ffma2(h2.x, w.x, a30); a31 = ffma2(h2.y, w.y, a31);
                w = *(const ulonglong2*)(p4 + k0 + ks);
                a40 = ffma2(c2.x, w.x, a40); a41 = ffma2(c2.y, w.y, a41);
                w = *(const ulonglong2*)(p5 + k0 + ks);
                a50 = ffma2(c2.x, w.x, a50); a51 = ffma2(c2.y, w.y, a51);
            }
        }

        float ai = fsum2(a00) + fsum2(a01) + fsum2(a40) + fsum2(a41) + p_i;
        float af = fsum2(a10) + fsum2(a11) + fsum2(a50) + fsum2(a51) + p_f;
        float ag = fsum2(a20) + fsum2(a21) + p_g;
        float po = fsum2(a30) + fsum2(a31) + p_o;

        float iv = 1.f / (1.f + expf(-ai));
        float fv = 1.f / (1.f + expf(-af));
        float gv = tanhf(ag);
        float cy = fmaf(fv, cin_own, iv * gv);
        c_out[idx] = cy;

        grid_barrier(tid);                 // all cy visible chip-wide

        // -------- phase 2: o = sig(po + cy @ w_cyo^T); h = o * tanh(cy) ----
        ull b0 = 0, b1 = 0, b2 = 0, b3 = 0;

        float4 r0 = __ldcv((const float4*)(c_out + sb0 * HH + kq0 * 4));
        float4 r1 = __ldcv((const float4*)(c_out + (sb0 + 16) * HH + kq0 * 4));

        for (int j = 0; j < 16; j++) {
            int k0 = j * 64;
            __syncthreads();
            *(float4*)hdst0 = r0;          // reuse sH as cy buffer
            *(float4*)hdst1 = r1;
            __syncthreads();
            if (j < 15) {
                int k1 = k0 + 64;
                r0 = __ldcv((const float4*)(c_out + sb0 * HH + k1 + kq0 * 4));
                r1 = __ldcv((const float4*)(c_out + (sb0 + 16) * HH + k1 + kq0 * 4));
            }
#pragma unroll
            for (int kq = 0; kq < 16; kq += 2) {
                int ks = kq * 4;
                ulonglong2 cc = *(const ulonglong2*)(shb + ks);
                ulonglong2 ww = *(const ulonglong2*)(wc + k0 + ks);
                b0 = ffma2(cc.x, ww.x, b0); b1 = ffma2(cc.y, ww.y, b1);
                ulonglong2 cc2 = *(const ulonglong2*)(shb + ks + 4);
                ulonglong2 ww2 = *(const ulonglong2*)(wc + k0 + ks + 4);
                b2 = ffma2(cc2.x, ww2.x, b2); b3 = ffma2(cc2.y, ww2.y, b3);
            }
        }

        float s = fsum2(b0) + fsum2(b1) + fsum2(b2) + fsum2(b3);
        float oo = 1.f / (1.f + expf(-(po + s)));
        float hy = oo * tanhf(cy);
        g_h[idx] = hy;
        out[(size_t)t * BH + idx] = hy;

        grid_barrier(tid);                 // h visible before next step
    }
}

// ---------------------------------------------------------------------------
extern "C" void kernel_launch(void* const* d_in, const int* in_sizes, int n_in,
                              void* d_out, int out_size)
{
    const float* X     = (const float*)d_in[0];
    const float* h0    = (const float*)d_in[1];
    const float* c0    = (const float*)d_in[2];
    const float* w_ii  = (const float*)d_in[3];
    const float* w_hi  = (const float*)d_in[4];
    const float* w_ci  = (const float*)d_in[5];
    const float* w_if  = (const float*)d_in[6];
    const float* w_hf  = (const float*)d_in[7];
    const float* w_cf  = (const float*)d_in[8];
    const float* w_ic  = (const float*)d_in[9];
    const float* w_hc  = (const float*)d_in[10];
    const float* w_io  = (const float*)d_in[11];
    const float* w_ho  = (const float*)d_in[12];
    const float* w_cyo = (const float*)d_in[13];
    const float* b_ii  = (const float*)d_in[14];
    const float* b_hi  = (const float*)d_in[15];
    const float* b_ci  = (const float*)d_in[16];
    const float* b_if  = (const float*)d_in[17];
    const float* b_hf  = (const float*)d_in[18];
    const float* b_cf  = (const float*)d_in[19];
    const float* b_ic  = (const float*)d_in[20];
    const float* b_hc  = (const float*)d_in[21];
    const float* b_io  = (const float*)d_in[22];
    const float* b_ho  = (const float*)d_in[23];
    const float* b_cyo = (const float*)d_in[24];
    float* out = (float*)d_out;

    cudaFuncSetAttribute(lstm_kernel,
                         cudaFuncAttributeMaxDynamicSharedMemorySize,
                         SMEM_FLOATS * 4);

    init_kernel<<<128, 256>>>(h0, c0, b_ii, b_hi, b_ci, b_if, b_hf, b_cf,
                              b_ic, b_hc, b_io, b_ho, b_cyo);
    proj_kernel<<<dim3(32, 128), 256>>>(X, w_ii, w_if, w_ic, w_io);
    lstm_kernel<<<NBLK, 256, SMEM_FLOATS * 4>>>(w_hi, w_hf, w_hc, w_ho,
                                                w_ci, w_cf, w_cyo, out);
}

// round 3
// speedup vs baseline: 1.0020x; 1.0020x over previous
#include <cuda_runtime.h>
#include <math.h>

#define TT 512
#define BB 32
#define II 512
#define HH 1024
#define BH (BB*HH)
#define TBH (TT*BB*HH)   // 16,777,216
#define NBLK 128
#define WROW 1032        // padded weight row (floats): 1032*4B -> 8-bank skew per row

typedef unsigned long long ull;

// ------------------------- device scratch (no allocations allowed) ----------
__device__ float g_P[(size_t)4 * TBH];   // 4 x [T][B][H] gate preactivations
__device__ float g_h[BH];                // hidden state
__device__ float g_c[2][BH];             // cell state ping-pong
__device__ float g_bias[4][HH];          // combined gate biases
__device__ unsigned g_bar_cnt;           // grid barrier arrival counter
__device__ unsigned g_bar_gen;           // grid barrier generation

// ------------------------- helpers -----------------------------------------
__device__ __forceinline__ ull ffma2(ull a, ull b, ull c) {
    ull d;
    asm("fma.rn.f32x2 %0, %1, %2, %3;" : "=l"(d) : "l"(a), "l"(b), "l"(c));
    return d;
}
__device__ __forceinline__ float fsum2(ull v) {
    float2 f = *(float2*)&v;
    return f.x + f.y;
}

__device__ __forceinline__ void grid_barrier(int tid) {
    __threadfence();                // make this thread's global writes visible
    __syncthreads();
    if (tid == 0) {
        unsigned g = *(volatile unsigned*)&g_bar_gen;
        unsigned old = atomicAdd(&g_bar_cnt, 1);
        if (old == NBLK - 1) {
            atomicExch(&g_bar_cnt, 0);
            __threadfence();
            atomicExch(&g_bar_gen, g + 1);
        } else {
            while (*(volatile unsigned*)&g_bar_gen == g) { __nanosleep(64); }
        }
    }
    __syncthreads();
}

// ------------------------- init --------------------------------------------
__global__ void __launch_bounds__(256) init_kernel(
    const float* __restrict__ h0, const float* __restrict__ c0,
    const float* __restrict__ b_ii, const float* __restrict__ b_hi,
    const float* __restrict__ b_ci, const float* __restrict__ b_if,
    const float* __restrict__ b_hf, const float* __restrict__ b_cf,
    const float* __restrict__ b_ic, const float* __restrict__ b_hc,
    const float* __restrict__ b_io, const float* __restrict__ b_ho,
    const float* __restrict__ b_cyo)
{
    int i = blockIdx.x * blockDim.x + threadIdx.x;
    if (i < BH) {
        g_h[i] = h0[i];
        g_c[0][i] = c0[i];
    }
    if (i < HH) {
        g_bias[0][i] = b_ii[i] + b_hi[i] + b_ci[i];
        g_bias[1][i] = b_if[i] + b_hf[i] + b_cf[i];
        g_bias[2][i] = b_ic[i] + b_hc[i];
        g_bias[3][i] = b_io[i] + b_ho[i] + b_cyo[i];
    }
    if (i == 0) { g_bar_cnt = 0; }
}

// ------------------------- proj: P = X @ W^T + bias ------------------------
// M=16384 (t*32+b), N'=4096 (4 gates x 1024), K=512. 128x128x8 SGEMM.
__global__ void __launch_bounds__(256) proj_kernel(
    const float* __restrict__ X,
    const float* __restrict__ Wii, const float* __restrict__ Wif,
    const float* __restrict__ Wic, const float* __restrict__ Wio)
{
    __shared__ float sA[8][128];
    __shared__ float sB[8][128];
    __shared__ float sBias[128];

    int tid = threadIdx.x;
    int bx = blockIdx.x;       // n tile (0..31)
    int by = blockIdx.y;       // m tile (0..127)
    int m0 = by * 128, n0 = bx * 128;

    if (tid < 128) {
        int np = n0 + tid;
        sBias[tid] = g_bias[np >> 10][np & 1023];
    }

    int lrow = tid >> 1;
    int lkq  = tid & 1;

    int np = n0 + lrow;
    int gsel = np >> 10;
    const float* wrow = (gsel == 0) ? Wii : (gsel == 1) ? Wif : (gsel == 2) ? Wic : Wio;
    wrow += (np & 1023) * II;

    const float* arow = X + (m0 + lrow) * II;

    int tx = tid & 15, ty = tid >> 4;

    float acc[8][8];
#pragma unroll
    for (int i = 0; i < 8; i++)
#pragma unroll
        for (int j = 0; j < 8; j++) acc[i][j] = 0.f;

    for (int k0 = 0; k0 < II; k0 += 8) {
        float4 av = *(const float4*)(arow + k0 + lkq * 4);
        float4 bv = *(const float4*)(wrow + k0 + lkq * 4);
        __syncthreads();
        sA[lkq * 4 + 0][lrow] = av.x; sA[lkq * 4 + 1][lrow] = av.y;
        sA[lkq * 4 + 2][lrow] = av.z; sA[lkq * 4 + 3][lrow] = av.w;
        sB[lkq * 4 + 0][lrow] = bv.x; sB[lkq * 4 + 1][lrow] = bv.y;
        sB[lkq * 4 + 2][lrow] = bv.z; sB[lkq * 4 + 3][lrow] = bv.w;
        __syncthreads();
#pragma unroll
        for (int kk = 0; kk < 8; kk++) {
            float a[8], b[8];
            *(float4*)(a)     = *(float4*)&sA[kk][ty * 4];
            *(float4*)(a + 4) = *(float4*)&sA[kk][64 + ty * 4];
            *(float4*)(b)     = *(float4*)&sB[kk][tx * 4];
            *(float4*)(b + 4) = *(float4*)&sB[kk][64 + tx * 4];
#pragma unroll
            for (int i = 0; i < 8; i++)
#pragma unroll
                for (int j = 0; j < 8; j++)
                    acc[i][j] = fmaf(a[i], b[j], acc[i][j]);
        }
    }

#pragma unroll
    for (int i = 0; i < 8; i++) {
        int m = m0 + ((i < 4) ? (ty * 4 + i) : (64 + ty * 4 + (i - 4)));
#pragma unroll
        for (int jh = 0; jh < 2; jh++) {
            int colbase = (jh ? 64 : 0) + tx * 4;
            int npc = n0 + colbase;
            int g = npc >> 10;
            int n = npc & 1023;
            float4 v;
            v.x = acc[i][jh * 4 + 0] + sBias[colbase + 0];
            v.y = acc[i][jh * 4 + 1] + sBias[colbase + 1];
            v.z = acc[i][jh * 4 + 2] + sBias[colbase + 2];
            v.w = acc[i][jh * 4 + 3] + sBias[colbase + 3];
            *(float4*)(g_P + (size_t)g * TBH + (size_t)m * HH + n) = v;
        }
    }
}

// ------------------------- persistent recurrence ---------------------------
// 128 blocks x 256 threads, 1 block/SM. Block owns 8 n-columns.
// Thread = (n_l = tid&7, b = tid>>3).
// SMEM: 6 weight mats [8][WROW] persistent + h/c chunk buffers [32][68].
#define SMEM_FLOATS (6*8*WROW + 2*32*68)

extern "C" __global__ void __launch_bounds__(256) lstm_kernel(
    const float* __restrict__ Whi, const float* __restrict__ Whf,
    const float* __restrict__ Whc, const float* __restrict__ Who,
    const float* __restrict__ Wci, const float* __restrict__ Wcf,
    const float* __restrict__ Wcyo, float* __restrict__ out)
{
    extern __shared__ float smem[];
    float* smw = smem;                   // 6*8*WROW
    float* sH  = smw + 6 * 8 * WROW;     // 32*68
    float* sC  = sH + 32 * 68;           // 32*68

    int tid = threadIdx.x;
    int n_l = tid & 7, b = tid >> 3;
    int n0 = blockIdx.x * 8;

    // ---- stage the 6 recurrent weight slices into SMEM once ----
    {
        const float* mats[6] = {Whi, Whf, Whc, Who, Wci, Wcf};
#pragma unroll
        for (int m = 0; m < 6; m++) {
            const float* src = mats[m] + (size_t)n0 * HH;
            float* dst = smw + m * 8 * WROW;
            for (int e = tid; e < 8 * 256; e += 256) {
                int r = e >> 8, kq = e & 255;
                *(float4*)(dst + r * WROW + kq * 4) =
                    *(const float4*)(src + r * HH + kq * 4);
            }
        }
    }
    __syncthreads();

    const float* p0 = smw + (0 * 8 + n_l) * WROW;   // w_hi
    const float* p1 = smw + (1 * 8 + n_l) * WROW;   // w_hf
    const float* p2 = smw + (2 * 8 + n_l) * WROW;   // w_hc
    const float* p3 = smw + (3 * 8 + n_l) * WROW;   // w_ho
    const float* p4 = smw + (4 * 8 + n_l) * WROW;   // w_ci
    const float* p5 = smw + (5 * 8 + n_l) * WROW;   // w_cf

    const int idx = b * HH + n0 + n_l;
    const float* wc = Wcyo + (size_t)(n0 + n_l) * HH;

    // staging assignments: thread stages rows sb0 and sb0+16, quad kq0
    const int sb0 = tid >> 4;        // 0..15
    const int kq0 = tid & 15;        // 0..15
    float* hdst0 = sH + sb0 * 68 + kq0 * 4;
    float* hdst1 = sH + (sb0 + 16) * 68 + kq0 * 4;
    float* cdst0 = sC + sb0 * 68 + kq0 * 4;
    float* cdst1 = sC + (sb0 + 16) * 68 + kq0 * 4;
    const float* shb = sH + b * 68;
    const float* scb = sC + b * 68;

    for (int t = 0; t < TT; t++) {
        const float* c_in  = g_c[t & 1];
        float*       c_out = g_c[(t + 1) & 1];
        size_t base = (size_t)t * BH + idx;

        float p_i = g_P[base];
        float p_f = g_P[(size_t)TBH + base];
        float p_g = g_P[2 * (size_t)TBH + base];
        float p_o = g_P[3 * (size_t)TBH + base];
        float cin_own = __ldcv(c_in + idx);

        ull a00 = 0, a01 = 0, a10 = 0, a11 = 0, a20 = 0, a21 = 0;
        ull a30 = 0, a31 = 0, a40 = 0, a41 = 0, a50 = 0, a51 = 0;

        // prefetch chunk 0 of h and c
        float4 rh0 = __ldcv((const float4*)(g_h  + sb0 * HH + kq0 * 4));
        float4 rh1 = __ldcv((const float4*)(g_h  + (sb0 + 16) * HH + kq0 * 4));
        float4 rc0 = __ldcv((const float4*)(c_in + sb0 * HH + kq0 * 4));
        float4 rc1 = __ldcv((const float4*)(c_in + (sb0 + 16) * HH + kq0 * 4));

        for (int j = 0; j < 16; j++) {
            int k0 = j * 64;
            __syncthreads();                // previous chunk's compute done
            *(float4*)hdst0 = rh0;
            *(float4*)hdst1 = rh1;
            *(float4*)cdst0 = rc0;
            *(float4*)cdst1 = rc1;
            __syncthreads();                // chunk visible
            if (j < 15) {
                int k1 = k0 + 64;
                rh0 = __ldcv((const float4*)(g_h  + sb0 * HH + k1 + kq0 * 4));
                rh1 = __ldcv((const float4*)(g_h  + (sb0 + 16) * HH + k1 + kq0 * 4));
                rc0 = __ldcv((const float4*)(c_in + sb0 * HH + k1 + kq0 * 4));
                rc1 = __ldcv((const float4*)(c_in + (sb0 + 16) * HH + k1 + kq0 * 4));
            }
#pragma unroll
            for (int kq = 0; kq < 16; kq++) {
                int ks = kq * 4;
                ulonglong2 h2 = *(const ulonglong2*)(shb + ks);
                ulonglong2 c2 = *(const ulonglong2*)(scb + ks);
                ulonglong2 w;
                w = *(const ulonglong2*)(p0 + k0 + ks);
                a00 = ffma2(h2.x, w.x, a00); a01 = ffma2(h2.y, w.y, a01);
                w = *(const ulonglong2*)(p1 + k0 + ks);
                a10 = ffma2(h2.x, w.x, a10); a11 = ffma2(h2.y, w.y, a11);
                w = *(const ulonglong2*)(p2 + k0 + ks);
                a20 = ffma2(h2.x, w.x, a20); a21 = ffma2(h2.y, w.y, a21);
                w = *(const ulonglong2*)(p3 + k0 + ks);
                a30 = ffma2(h2.x, w.x, a30); a31 = ffma2(h2.y, w.y, a31);
                w = *(const ulonglong2*)(p4 + k0 + ks);
                a40 = ffma2(c2.x, w.x, a40); a41 = ffma2(c2.y, w.y, a41);
                w = *(const ulonglong2*)(p5 + k0 + ks);
                a50 = ffma2(c2.x, w.x, a50); a51 = ffma2(c2.y, w.y, a51);
            }
        }

        float ai = fsum2(a00) + fsum2(a01) + fsum2(a40) + fsum2(a41) + p_i;
        float af = fsum2(a10) + fsum2(a11) + fsum2(a50) + fsum2(a51) + p_f;
        float ag = fsum2(a20) + fsum2(a21) + p_g;
        float po = fsum2(a30) + fsum2(a31) + p_o;

        float iv = 1.f / (1.f + expf(-ai));
        float fv = 1.f / (1.f + expf(-af));
        float gv = tanhf(ag);
        float cy = fmaf(fv, cin_own, iv * gv);
        c_out[idx] = cy;

        grid_barrier(tid);                 // all cy visible chip-wide

        // -------- phase 2: o = sig(po + cy @ w_cyo^T); h = o * tanh(cy) ----
        ull b0 = 0, b1 = 0, b2 = 0, b3 = 0;

        float4 r0 = __ldcv((const float4*)(c_out + sb0 * HH + kq0 * 4));
        float4 r1 = __ldcv((const float4*)(c_out + (sb0 + 16) * HH + kq0 * 4));

        for (int j = 0; j < 16; j++) {
            int k0 = j * 64;
            __syncthreads();
            *(float4*)hdst0 = r0;          // reuse sH as cy buffer
            *(float4*)hdst1 = r1;
            __syncthreads();
            if (j < 15) {
                int k1 = k0 + 64;
                r0 = __ldcv((const float4*)(c_out + sb0 * HH + k1 + kq0 * 4));
                r1 = __ldcv((const float4*)(c_out + (sb0 + 16) * HH + k1 + kq0 * 4));
            }
#pragma unroll
            for (int kq = 0; kq < 16; kq += 2) {
                int ks = kq * 4;
                ulonglong2 cc = *(const ulonglong2*)(shb + ks);
                ulonglong2 ww = *(const ulonglong2*)(wc + k0 + ks);
                b0 = ffma2(cc.x, ww.x, b0); b1 = ffma2(cc.y, ww.y, b1);
                ulonglong2 cc2 = *(const ulonglong2*)(shb + ks + 4);
                ulonglong2 ww2 = *(const ulonglong2*)(wc + k0 + ks + 4);
                b2 = ffma2(cc2.x, ww2.x, b2); b3 = ffma2(cc2.y, ww2.y, b3);
            }
        }

        float s = fsum2(b0) + fsum2(b1) + fsum2(b2) + fsum2(b3);
        float oo = 1.f / (1.f + expf(-(po + s)));
        float hy = oo * tanhf(cy);
        g_h[idx] = hy;
        out[(size_t)t * BH + idx] = hy;

        grid_barrier(tid);                 // h visible before next step
    }
}

// ---------------------------------------------------------------------------
extern "C" void kernel_launch(void* const* d_in, const int* in_sizes, int n_in,
                              void* d_out, int out_size)
{
    const float* X     = (const float*)d_in[0];
    const float* h0    = (const float*)d_in[1];
    const float* c0    = (const float*)d_in[2];
    const float* w_ii  = (const float*)d_in[3];
    const float* w_hi  = (const float*)d_in[4];
    const float* w_ci  = (const float*)d_in[5];
    const float* w_if  = (const float*)d_in[6];
    const float* w_hf  = (const float*)d_in[7];
    const float* w_cf  = (const float*)d_in[8];
    const float* w_ic  = (const float*)d_in[9];
    const float* w_hc  = (const float*)d_in[10];
    const float* w_io  = (const float*)d_in[11];
    const float* w_ho  = (const float*)d_in[12];
    const float* w_cyo = (const float*)d_in[13];
    const float* b_ii  = (const float*)d_in[14];
    const float* b_hi  = (const float*)d_in[15];
    const float* b_ci  = (const float*)d_in[16];
    const float* b_if  = (const float*)d_in[17];
    const float* b_hf  = (const float*)d_in[18];
    const float* b_cf  = (const float*)d_in[19];
    const float* b_ic  = (const float*)d_in[20];
    const float* b_hc  = (const float*)d_in[21];
    const float* b_io  = (const float*)d_in[22];
    const float* b_ho  = (const float*)d_in[23];
    const float* b_cyo = (const float*)d_in[24];
    float* out = (float*)d_out;

    cudaFuncSetAttribute(lstm_kernel,
                         cudaFuncAttributeMaxDynamicSharedMemorySize,
                         SMEM_FLOATS * 4);

    init_kernel<<<128, 256>>>(h0, c0, b_ii, b_hi, b_ci, b_if, b_hf, b_cf,
                              b_ic, b_hc, b_io, b_ho, b_cyo);
    proj_kernel<<<dim3(32, 128), 256>>>(X, w_ii, w_if, w_ic, w_io);
    lstm_kernel<<<NBLK, 256, SMEM_FLOATS * 4>>>(w_hi, w_hf, w_hc, w_ho,
                                                w_ci, w_cf, w_cyo, out);
}

// round 4
// speedup vs baseline: 3.4747x; 3.4678x over previous
#include <cuda_runtime.h>
#include <math.h>

#define TT 512
#define BB 32
#define II 512
#define HH 1024
#define BH (BB*HH)
#define TBH (TT*BB*HH)
#define NBLK 128

__device__ float g_P[(size_t)4 * TBH];
__device__ float g_h[BH];
__device__ float g_c[2][BH];
__device__ float g_po[BH];
__device__ float g_acc[6 * 1024 * 32];
__device__ float g_bias[4][HH];
__device__ float g_Wpk[(size_t)7 * 64 * 16384];  // fragment-packed tf32 weights
__device__ unsigned g_cnt;
__device__ volatile unsigned g_gen;

__device__ __forceinline__ unsigned cvt_tf32(float x) {
    unsigned r; asm("cvt.rna.tf32.f32 %0, %1;" : "=r"(r) : "f"(x)); return r;
}
__device__ __forceinline__ void st4tf(float* p, float4 v) {
    uint4 u; u.x = cvt_tf32(v.x); u.y = cvt_tf32(v.y);
    u.z = cvt_tf32(v.z); u.w = cvt_tf32(v.w); *(uint4*)p = u;
}
__device__ __forceinline__ void mma_tf32(float* d, uint4 a, unsigned b0, unsigned b1) {
    asm("mma.sync.aligned.m16n8k8.row.col.f32.tf32.tf32.f32 "
        "{%0,%1,%2,%3},{%4,%5,%6,%7},{%8,%9},{%0,%1,%2,%3};"
        : "+f"(d[0]), "+f"(d[1]), "+f"(d[2]), "+f"(d[3])
        : "r"(a.x), "r"(a.y), "r"(a.z), "r"(a.w), "r"(b0), "r"(b1));
}
__device__ __forceinline__ void gbar(unsigned target) {
    __syncthreads();
    if (threadIdx.x == 0) {
        __threadfence();
        unsigned old = atomicAdd(&g_cnt, 1);
        if (old == NBLK - 1) { g_cnt = 0; __threadfence(); g_gen = target; }
        else { while (g_gen < target) { } __threadfence(); }
    }
    __syncthreads();
}

__global__ void __launch_bounds__(256) init_kernel(
    const float* __restrict__ h0, const float* __restrict__ c0,
    const float* __restrict__ b_ii, const float* __restrict__ b_hi,
    const float* __restrict__ b_ci, const float* __restrict__ b_if,
    const float* __restrict__ b_hf, const float* __restrict__ b_cf,
    const float* __restrict__ b_ic, const float* __restrict__ b_hc,
    const float* __restrict__ b_io, const float* __restrict__ b_ho,
    const float* __restrict__ b_cyo)
{
    int i = blockIdx.x * blockDim.x + threadIdx.x;
    if (i < BH) { g_h[i] = h0[i]; g_c[0][i] = c0[i]; }
    if (i < HH) {
        g_bias[0][i] = b_ii[i] + b_hi[i] + b_ci[i];
        g_bias[1][i] = b_if[i] + b_hf[i] + b_cf[i];
        g_bias[2][i] = b_ic[i] + b_hc[i];
        g_bias[3][i] = b_io[i] + b_ho[i] + b_cyo[i];
    }
    if (i == 0) { g_cnt = 0; g_gen = 0; }
}

// pack 7 HxH matrices into m16n8k8 A-fragment order:
// [tile = mat*64+ng][ktile 0..127][lane 0..31][jj 0..3]
__global__ void __launch_bounds__(256) pack_kernel(
    const float* __restrict__ w0, const float* __restrict__ w1,
    const float* __restrict__ w2, const float* __restrict__ w3,
    const float* __restrict__ w4, const float* __restrict__ w5,
    const float* __restrict__ w6)
{
    int gid = blockIdx.x * 256 + threadIdx.x;
    int mat = gid >> 20, rem = gid & 1048575;
    int ng = rem >> 14, kt = (rem >> 7) & 127, lane = (rem >> 2) & 31, jj = rem & 3;
    int row = ng * 16 + (lane >> 2) + 8 * (jj & 1);
    int col = kt * 8 + (lane & 3) + 4 * (jj >> 1);
    const float* W = (mat == 0) ? w0 : (mat == 1) ? w1 : (mat == 2) ? w2 :
                     (mat == 3) ? w3 : (mat == 4) ? w4 : (mat == 5) ? w5 : w6;
    g_Wpk[gid] = __uint_as_float(cvt_tf32(__ldg(&W[row * HH + col])));
}

// proj: P[g][m][n] = X @ Wg^T + bias (fp32 SGEMM 128x128x8)
__global__ void __launch_bounds__(256) proj_kernel(
    const float* __restrict__ X,
    const float* __restrict__ Wii, const float* __restrict__ Wif,
    const float* __restrict__ Wic, const float* __restrict__ Wio)
{
    __shared__ float sA[8][128];
    __shared__ float sB[8][128];
    __shared__ float sBias[128];
    int tid = threadIdx.x;
    int m0 = blockIdx.y * 128, n0 = blockIdx.x * 128;
    if (tid < 128) { int np = n0 + tid; sBias[tid] = g_bias[np >> 10][np & 1023]; }
    int lrow = tid >> 1, lkq = tid & 1;
    int np = n0 + lrow, gsel = np >> 10;
    const float* wrow = (gsel == 0) ? Wii : (gsel == 1) ? Wif : (gsel == 2) ? Wic : Wio;
    wrow += (np & 1023) * II;
    const float* arow = X + (m0 + lrow) * II;
    int tx = tid & 15, ty = tid >> 4;
    float acc[8][8];
#pragma unroll
    for (int i = 0; i < 8; i++)
#pragma unroll
        for (int j = 0; j < 8; j++) acc[i][j] = 0.f;
    for (int k0 = 0; k0 < II; k0 += 8) {
        float4 av = *(const float4*)(arow + k0 + lkq * 4);
        float4 bv = *(const float4*)(wrow + k0 + lkq * 4);
        __syncthreads();
        sA[lkq * 4 + 0][lrow] = av.x; sA[lkq * 4 + 1][lrow] = av.y;
        sA[lkq * 4 + 2][lrow] = av.z; sA[lkq * 4 + 3][lrow] = av.w;
        sB[lkq * 4 + 0][lrow] = bv.x; sB[lkq * 4 + 1][lrow] = bv.y;
        sB[lkq * 4 + 2][lrow] = bv.z; sB[lkq * 4 + 3][lrow] = bv.w;
        __syncthreads();
#pragma unroll
        for (int kk = 0; kk < 8; kk++) {
            float a[8], b[8];
            *(float4*)(a) = *(float4*)&sA[kk][ty * 4];
            *(float4*)(a + 4) = *(float4*)&sA[kk][64 + ty * 4];
            *(float4*)(b) = *(float4*)&sB[kk][tx * 4];
            *(float4*)(b + 4) = *(float4*)&sB[kk][64 + tx * 4];
#pragma unroll
            for (int i = 0; i < 8; i++)
#pragma unroll
                for (int j = 0; j < 8; j++) acc[i][j] = fmaf(a[i], b[j], acc[i][j]);
        }
    }
#pragma unroll
    for (int i = 0; i < 8; i++) {
        int m = m0 + ((i < 4) ? (ty * 4 + i) : (64 + ty * 4 + (i - 4)));
#pragma unroll
        for (int jh = 0; jh < 2; jh++) {
            int colbase = (jh ? 64 : 0) + tx * 4;
            int npc = n0 + colbase;
            float4 v;
            v.x = acc[i][jh * 4 + 0] + sBias[colbase + 0];
            v.y = acc[i][jh * 4 + 1] + sBias[colbase + 1];
            v.z = acc[i][jh * 4 + 2] + sBias[colbase + 2];
            v.w = acc[i][jh * 4 + 3] + sBias[colbase + 3];
            *(float4*)(g_P + (size_t)(npc >> 10) * TBH + (size_t)m * HH + (npc & 1023)) = v;
        }
    }
}

// persistent tf32 recurrence: 128 blocks x 256 thr (8 warps = 4 ksplit x 2 bhalf)
#define SMEM_FLOATS (49152 + 8704)

extern "C" __global__ void __launch_bounds__(256) lstm_kernel(float* __restrict__ out)
{
    extern __shared__ float smem[];
    float* sW  = smem;              // 3 tiles x 16384
    float* sB  = smem + 49152;      // staging / reduction area (8704)
    float* sBh = sB;                // 2 x 2176
    float* sBc = sB + 2 * 2176;     // 2 x 2176 (phase1) / 2 x 1088 (phase2 A)

    const int tid = threadIdx.x, bId = blockIdx.x;
    const int w = tid >> 5, lane = tid & 31;
    const int kw = w >> 1, bgset = w & 1;

    const int s0 = 3 * bId;
    const int mats[3] = { s0 >> 6, (s0 + 1) >> 6, (s0 + 2) >> 6 };
    const bool uC0 = mats[0] >= 4, uC1 = mats[1] >= 4, uC2 = mats[2] >= 4;
    const bool needH = !(uC0 && uC1 && uC2);
    const bool needC = uC0 || uC1 || uC2;

#pragma unroll
    for (int tt = 0; tt < 3; tt++) {
        const float4* src = (const float4*)(g_Wpk + (size_t)(s0 + tt) * 16384);
        float4* dst = (float4*)(sW + tt * 16384);
        for (int p = tid; p < 4096; p += 256) dst[p] = __ldg(src + p);
    }

    const int v1 = tid + 256;
    const int b0s = tid >> 4, kq0 = (tid & 15) * 4;
    const int b1s = v1 >> 4,  kq1 = (v1 & 15) * 4;
    const int brow0 = (bgset * 16 + (lane >> 2)) * 68 + (lane & 3);
    const int brow1 = (bgset * 16 + 8 + (lane >> 2)) * 68 + (lane & 3);

    unsigned bar = 0;
    __syncthreads();

    for (int t = 0; t < TT; t++) {
        const int cur = t & 1, nxt = cur ^ 1;
        const float* c_in = g_c[cur];

        // ---------- phase 1: [Whi;Whf;Whc;Who;Wci;Wcf] GEMM ----------
        float acc[3][2][4];
#pragma unroll
        for (int a = 0; a < 3; a++)
#pragma unroll
            for (int g = 0; g < 2; g++)
#pragma unroll
                for (int j = 0; j < 4; j++) acc[a][g][j] = 0.f;

        float4 ph0, ph1, pc0, pc1;
        if (needH) {
            ph0 = __ldcg((const float4*)(g_h + b0s * HH + kq0));
            ph1 = __ldcg((const float4*)(g_h + b1s * HH + kq1));
        }
        if (needC) {
            pc0 = __ldcg((const float4*)(c_in + b0s * HH + kq0));
            pc1 = __ldcg((const float4*)(c_in + b1s * HH + kq1));
        }

        for (int j = 0; j < 16; j++) {
            float* bh = sBh + (j & 1) * 2176;
            float* bc = sBc + (j & 1) * 2176;
            __syncthreads();
            if (needH) { st4tf(bh + b0s * 68 + kq0, ph0); st4tf(bh + b1s * 68 + kq1, ph1); }
            if (needC) { st4tf(bc + b0s * 68 + kq0, pc0); st4tf(bc + b1s * 68 + kq1, pc1); }
            __syncthreads();
            if (j < 15) {
                int k1 = (j + 1) * 64;
                if (needH) {
                    ph0 = __ldcg((const float4*)(g_h + b0s * HH + k1 + kq0));
                    ph1 = __ldcg((const float4*)(g_h + b1s * HH + k1 + kq1));
                }
                if (needC) {
                    pc0 = __ldcg((const float4*)(c_in + b0s * HH + k1 + kq0));
                    pc1 = __ldcg((const float4*)(c_in + b1s * HH + k1 + kq1));
                }
            }
#pragma unroll
            for (int q = 0; q < 2; q++) {
                const int kt = kw * 2 + q, colo = kt * 8;
                unsigned h0a = 0, h1a = 0, h0b = 0, h1b = 0;
                unsigned c0a = 0, c1a = 0, c0b = 0, c1b = 0;
                if (needH) {
                    h0a = *(const unsigned*)(bh + brow0 + colo);
                    h1a = *(const unsigned*)(bh + brow0 + colo + 4);
                    h0b = *(const unsigned*)(bh + brow1 + colo);
                    h1b = *(const unsigned*)(bh + brow1 + colo + 4);
                }
                if (needC) {
                    c0a = *(const unsigned*)(bc + brow0 + colo);
                    c1a = *(const unsigned*)(bc + brow0 + colo + 4);
                    c0b = *(const unsigned*)(bc + brow1 + colo);
                    c1b = *(const unsigned*)(bc + brow1 + colo + 4);
                }
                const int gkt = j * 8 + kt;
                uint4 a0 = *(const uint4*)(sW + gkt * 128 + lane * 4);
                uint4 a1 = *(const uint4*)(sW + 16384 + gkt * 128 + lane * 4);
                uint4 a2 = *(const uint4*)(sW + 32768 + gkt * 128 + lane * 4);
                mma_tf32(acc[0][0], a0, uC0 ? c0a : h0a, uC0 ? c1a : h1a);
                mma_tf32(acc[0][1], a0, uC0 ? c0b : h0b, uC0 ? c1b : h1b);
                mma_tf32(acc[1][0], a1, uC1 ? c0a : h0a, uC1 ? c1a : h1a);
                mma_tf32(acc[1][1], a1, uC1 ? c0b : h0b, uC1 ? c1b : h1b);
                mma_tf32(acc[2][0], a2, uC2 ? c0a : h0a, uC2 ? c1a : h1a);
                mma_tf32(acc[2][1], a2, uC2 ? c0b : h0b, uC2 ? c1b : h1b);
            }
        }

        __syncthreads();
        if (kw > 0) {
            float* dst = sB + (((kw - 1) * 2 + bgset) * 32 + lane) * 24;
#pragma unroll
            for (int a = 0; a < 3; a++)
#pragma unroll
                for (int g = 0; g < 2; g++)
#pragma unroll
                    for (int j = 0; j < 4; j++) dst[a * 8 + g * 4 + j] = acc[a][g][j];
        }
        __syncthreads();
        if (kw == 0) {
#pragma unroll
            for (int r = 0; r < 3; r++) {
                const float* sp = sB + ((r * 2 + bgset) * 32 + lane) * 24;
#pragma unroll
                for (int a = 0; a < 3; a++)
#pragma unroll
                    for (int g = 0; g < 2; g++)
#pragma unroll
                        for (int j = 0; j < 4; j++) acc[a][g][j] += sp[a * 8 + g * 4 + j];
            }
#pragma unroll
            for (int a = 0; a < 3; a++) {
                const int mat = (s0 + a) >> 6, ng = (s0 + a) & 63;
#pragma unroll
                for (int g = 0; g < 2; g++)
#pragma unroll
                    for (int j = 0; j < 4; j++) {
                        int row = ng * 16 + (lane >> 2) + 8 * (j >> 1);
                        int bcol = bgset * 16 + g * 8 + 2 * (lane & 3) + (j & 1);
                        g_acc[((mat << 10) + row) * 32 + bcol] = acc[a][g][j];
                    }
            }
        }
        gbar(++bar);

        // ---------- pointwise: gates, cy ----------
        {
            int idx = bId * 256 + tid;
            int n = idx >> 5, b = idx & 31;
            int off = b * HH + n;
            size_t pb = (size_t)t * BH + off;
            float hi = __ldcg(&g_acc[n * 32 + b]);
            float hf = __ldcg(&g_acc[(1024 + n) * 32 + b]);
            float hc = __ldcg(&g_acc[(2048 + n) * 32 + b]);
            float ho = __ldcg(&g_acc[(3072 + n) * 32 + b]);
            float ci = __ldcg(&g_acc[(4096 + n) * 32 + b]);
            float cf = __ldcg(&g_acc[(5120 + n) * 32 + b]);
            float cold = __ldcg(&g_c[cur][off]);
            float pi = __ldg(&g_P[pb]) + hi + ci;
            float pf = __ldg(&g_P[(size_t)TBH + pb]) + hf + cf;
            float pg = __ldg(&g_P[2 * (size_t)TBH + pb]) + hc;
            float po = __ldg(&g_P[3 * (size_t)TBH + pb]) + ho;
            float iv = 1.f / (1.f + expf(-pi));
            float fv = 1.f / (1.f + expf(-pf));
            float gv = tanhf(pg);
            float cy = fmaf(fv, cold, iv * gv);
            g_c[nxt][off] = cy;
            g_po[off] = po;
        }
        gbar(++bar);

        // ---------- phase 2: cy @ Wcyo^T -> o, h ----------
        if (bId < 64) {
            float acc2[2][4];
#pragma unroll
            for (int g = 0; g < 2; g++)
#pragma unroll
                for (int j = 0; j < 4; j++) acc2[g][j] = 0.f;

            float* sCy = sBh;
            float* sA2 = sBc;
            const float* cyp = g_c[nxt];
            const float* wsrc = g_Wpk + (size_t)(384 + bId) * 16384;

            float4 py0 = __ldcg((const float4*)(cyp + b0s * HH + kq0));
            float4 py1 = __ldcg((const float4*)(cyp + b1s * HH + kq1));
            float4 pa  = __ldg((const float4*)(wsrc) + tid);

            for (int j = 0; j < 16; j++) {
                float* cb = sCy + (j & 1) * 2176;
                float* ab = sA2 + (j & 1) * 1088;
                __syncthreads();
                st4tf(cb + b0s * 68 + kq0, py0);
                st4tf(cb + b1s * 68 + kq1, py1);
                *(float4*)(ab + tid * 4) = pa;
                __syncthreads();
                if (j < 15) {
                    int k1 = (j + 1) * 64;
                    py0 = __ldcg((const float4*)(cyp + b0s * HH + k1 + kq0));
                    py1 = __ldcg((const float4*)(cyp + b1s * HH + k1 + kq1));
                    pa  = __ldg((const float4*)(wsrc + (j + 1) * 1024) + tid);
                }
#pragma unroll
                for (int q = 0; q < 2; q++) {
                    const int kt = kw * 2 + q, colo = kt * 8;
                    unsigned y0a = *(const unsigned*)(cb + brow0 + colo);
                    unsigned y1a = *(const unsigned*)(cb + brow0 + colo + 4);
                    unsigned y0b = *(const unsigned*)(cb + brow1 + colo);
                    unsigned y1b = *(const unsigned*)(cb + brow1 + colo + 4);
                    uint4 af = *(const uint4*)(ab + kt * 128 + lane * 4);
                    mma_tf32(acc2[0], af, y0a, y1a);
                    mma_tf32(acc2[1], af, y0b, y1b);
                }
            }

            __syncthreads();
            if (kw > 0) {
                float* dst = sCy + (((kw - 1) * 2 + bgset) * 32 + lane) * 8;
#pragma unroll
                for (int g = 0; g < 2; g++)
#pragma unroll
                    for (int j = 0; j < 4; j++) dst[g * 4 + j] = acc2[g][j];
            }
            __syncthreads();
            if (kw == 0) {
#pragma unroll
                for (int r = 0; r < 3; r++) {
                    const float* sp = sCy + ((r * 2 + bgset) * 32 + lane) * 8;
#pragma unroll
                    for (int g = 0; g < 2; g++)
#pragma unroll
                        for (int j = 0; j < 4; j++) acc2[g][j] += sp[g * 4 + j];
                }
#pragma unroll
                for (int g = 0; g < 2; g++)
#pragma unroll
                    for (int j = 0; j < 4; j++) {
                        int row = bId * 16 + (lane >> 2) + 8 * (j >> 1);
                        int bcol = bgset * 16 + g * 8 + 2 * (lane & 3) + (j & 1);
                        int off = bcol * HH + row;
                        float po = __ldcg(&g_po[off]);
                        float cyv = __ldcg(&g_c[nxt][off]);
                        float o = 1.f / (1.f + expf(-(po + acc2[g][j])));
                        float hy = o * tanhf(cyv);
                        g_h[off] = hy;
                        out[(size_t)t * BH + off] = hy;
                    }
            }
        }
        gbar(++bar);
    }
}

extern "C" void kernel_launch(void* const* d_in, const int* in_sizes, int n_in,
                              void* d_out, int out_size)
{
    const float* X     = (const float*)d_in[0];
    const float* h0    = (const float*)d_in[1];
    const float* c0    = (const float*)d_in[2];
    const float* w_ii  = (const float*)d_in[3];
    const float* w_hi  = (const float*)d_in[4];
    const float* w_ci  = (const float*)d_in[5];
    const float* w_if  = (const float*)d_in[6];
    const float* w_hf  = (const float*)d_in[7];
    const float* w_cf  = (const float*)d_in[8];
    const float* w_ic  = (const float*)d_in[9];
    const float* w_hc  = (const float*)d_in[10];
    const float* w_io  = (const float*)d_in[11];
    const float* w_ho  = (const float*)d_in[12];
    const float* w_cyo = (const float*)d_in[13];
    float* out = (float*)d_out;

    cudaFuncSetAttribute(lstm_kernel,
                         cudaFuncAttributeMaxDynamicSharedMemorySize,
                         SMEM_FLOATS * 4);

    init_kernel<<<128, 256>>>(h0, c0,
        (const float*)d_in[14], (const float*)d_in[15], (const float*)d_in[16],
        (const float*)d_in[17], (const float*)d_in[18], (const float*)d_in[19],
        (const float*)d_in[20], (const float*)d_in[21], (const float*)d_in[22],
        (const float*)d_in[23], (const float*)d_in[24]);
    pack_kernel<<<28672, 256>>>(w_hi, w_hf, w_hc, w_ho, w_ci, w_cf, w_cyo);
    proj_kernel<<<dim3(32, 128), 256>>>(X, w_ii, w_if, w_ic, w_io);
    lstm_kernel<<<NBLK, 256, SMEM_FLOATS * 4>>>(out);
}